// round 15
// baseline (speedup 1.0000x reference)
#include <cuda_runtime.h>
#include <cuda_bf16.h>
#include <stdint.h>
#include <math.h>
#include <float.h>

#define PI_F 3.14159265358979323846f
#define CAP 32768

// ===================== static scratch =====================
__device__ float2 g_spec[16 * 512 * 512];
__device__ float  g_mag [16 * 512 * 512];
__device__ float  g_h1  [16 * 32 * 256 * 256];
__device__ float  g_cand[16 * CAP];
__device__ int    g_mhist[16 * 4096];
__device__ int    g_thresh[16];
__device__ int    g_cnt[16];
__device__ float  g_dom [16 * 128];
__device__ float  g_sims[16 * 64];
__device__ float  g_pool[16 * 64 * 16];
__device__ double g_psum[16];
__device__ double g_psumsq[16];
__device__ int    g_hist[16 * 64];

// ===================== mma helpers =====================
__device__ __forceinline__ void split2(float f0, float f1, unsigned& hi, unsigned& lo) {
    unsigned b0 = __float_as_uint(f0) & 0xFFFF0000u;
    unsigned b1 = __float_as_uint(f1) & 0xFFFF0000u;
    hi = (b0 >> 16) | b1;
    float l0 = f0 - __uint_as_float(b0);
    float l1 = f1 - __uint_as_float(b1);
    asm("cvt.rn.bf16x2.f32 %0, %1, %2;" : "=r"(lo) : "f"(l1), "f"(l0));
}
__device__ __forceinline__ void mma16816(float* c, const unsigned* a, const unsigned* b) {
    asm volatile("mma.sync.aligned.m16n8k16.row.col.f32.bf16.bf16.f32 "
        "{%0,%1,%2,%3}, {%4,%5,%6,%7}, {%8,%9}, {%0,%1,%2,%3};"
        : "+f"(c[0]), "+f"(c[1]), "+f"(c[2]), "+f"(c[3])
        : "r"(a[0]), "r"(a[1]), "r"(a[2]), "r"(a[3]), "r"(b[0]), "r"(b[1]));
}

// ===================== init =====================
__global__ void zero_k() {
    int tid = blockIdx.x * blockDim.x + threadIdx.x;
    int nt = gridDim.x * blockDim.x;
    for (int i = tid; i < 16 * 64 * 16; i += nt) g_pool[i] = 0.f;
    for (int i = tid; i < 16 * 64; i += nt) g_hist[i] = 0;
    for (int i = tid; i < 16 * 4096; i += nt) g_mhist[i] = 0;
    for (int i = tid; i < 16; i += nt) { g_psum[i] = 0.0; g_psumsq[i] = 0.0; g_cnt[i] = 0; }
}

// ===================== batched 512-pt FFT (256 threads, 2 FFTs per block) =====================
__device__ __forceinline__ void fft512x2(float2 (*s)[512], const float2* tw) {
    int tid = threadIdx.x;
    __syncthreads();
    #pragma unroll
    for (int f = 0; f < 2; ++f)
        for (int i = tid; i < 512; i += 256) {
            int j = __brev(i) >> 23;
            if (j > i) { float2 t = s[f][i]; s[f][i] = s[f][j]; s[f][j] = t; }
        }
    __syncthreads();
    #pragma unroll
    for (int st = 0; st < 9; ++st) {
        int half = 1 << st;
        int pos = tid & (half - 1);
        int i0 = ((tid >> st) << (st + 1)) + pos;
        int i1 = i0 + half;
        float2 w = tw[pos << (8 - st)];
        #pragma unroll
        for (int f = 0; f < 2; ++f) {
            float2 a = s[f][i0], b = s[f][i1];
            float2 t = make_float2(w.x * b.x - w.y * b.y, w.x * b.y + w.y * b.x);
            s[f][i0] = make_float2(a.x + t.x, a.y + t.y);
            s[f][i1] = make_float2(a.x - t.x, a.y - t.y);
        }
        __syncthreads();
    }
}

__global__ void __launch_bounds__(256) fft_rows_k(const float* __restrict__ img) {
    __shared__ float2 s[2][512];
    __shared__ float2 tw[256];
    int b = blockIdx.x >> 7, rg = blockIdx.x & 127;
    int row0 = rg * 4;
    int tid = threadIdx.x;
    const float* p = img + (((size_t)b << 9) + row0) * 512;
    for (int i = tid; i < 512; i += 256) {
        s[0][i] = make_float2(p[i], p[512 + i]);
        s[1][i] = make_float2(p[1024 + i], p[1536 + i]);
    }
    { float sc, cc; sincosf(-2.f * PI_F * (float)tid / 512.f, &sc, &cc); tw[tid] = make_float2(cc, sc); }
    fft512x2(s, tw);
    __syncthreads();
    for (int k = tid; k < 512; k += 256) {
        int nk = (512 - k) & 511;
        #pragma unroll
        for (int f = 0; f < 2; ++f) {
            float2 A = s[f][k], B = s[f][nk];
            float2 X = make_float2(0.5f * (A.x + B.x), 0.5f * (A.y - B.y));
            float2 Y = make_float2(0.5f * (A.y + B.y), 0.5f * (B.x - A.x));
            size_t base = (((size_t)(b * 512 + k)) << 9) + row0 + 2 * f;
            g_spec[base] = X;
            g_spec[base + 1] = Y;
        }
    }
}

__global__ void __launch_bounds__(256) fft_cols_k() {
    __shared__ float2 s[2][512];
    __shared__ float2 tw[256];
    __shared__ float rsum[256], rsq[256];
    __shared__ int lhist[64];
    int b = blockIdx.x >> 8;
    int tid = threadIdx.x;
    size_t base0 = ((size_t)blockIdx.x) << 10;
    for (int i = tid; i < 512; i += 256) {
        s[0][i] = g_spec[base0 + i];
        s[1][i] = g_spec[base0 + 512 + i];
    }
    { float sc, cc; sincosf(-2.f * PI_F * (float)tid / 512.f, &sc, &cc); tw[tid] = make_float2(cc, sc); }
    if (tid < 64) lhist[tid] = 0;
    fft512x2(s, tw);
    __syncthreads();
    float lsum = 0.f, lsq = 0.f;
    #pragma unroll
    for (int f = 0; f < 2; ++f)
        for (int i = tid; i < 512; i += 256) {
            float2 v = s[f][i];
            g_mag[base0 + f * 512 + i] = sqrtf(v.x * v.x + v.y * v.y);
            float ph = atan2f(v.y, v.x);
            lsum += ph; lsq += ph * ph;
            int bin = (int)floorf((ph + PI_F) * (64.f / (2.f * PI_F)));
            bin = min(max(bin, 0), 63);
            atomicAdd(&lhist[bin], 1);
        }
    rsum[tid] = lsum; rsq[tid] = lsq;
    __syncthreads();
    for (int st = 128; st > 0; st >>= 1) {
        if (tid < st) { rsum[tid] += rsum[tid + st]; rsq[tid] += rsq[tid + st]; }
        __syncthreads();
    }
    if (tid == 0) {
        atomicAdd(&g_psum[b], (double)rsum[0]);
        atomicAdd(&g_psumsq[b], (double)rsq[0]);
    }
    if (tid < 64) atomicAdd(&g_hist[b * 64 + tid], lhist[tid]);
}

// ===================== exact top-128 via histogram threshold =====================
__global__ void __launch_bounds__(256) maghist_k() {
    __shared__ int h[4096];
    int b = blockIdx.x >> 4, seg = blockIdx.x & 15;
    int tid = threadIdx.x;
    for (int i = tid; i < 4096; i += 256) h[i] = 0;
    __syncthreads();
    size_t base = ((size_t)b << 18) + ((size_t)seg << 14);
    for (int i = tid; i < 16384; i += 256) {
        unsigned bits = __float_as_uint(g_mag[base + i]);
        atomicAdd(&h[bits >> 19], 1);
    }
    __syncthreads();
    for (int i = tid; i < 4096; i += 256)
        if (h[i]) atomicAdd(&g_mhist[b * 4096 + i], h[i]);
}

__global__ void thresh_k() {
    int b = blockIdx.x;
    if (threadIdx.x == 0) {
        int acc = 0, t = 0;
        for (int i = 4095; i >= 0; --i) {
            acc += g_mhist[b * 4096 + i];
            if (acc >= 128) { t = i; break; }
        }
        g_thresh[b] = t;
    }
}

__global__ void __launch_bounds__(256) compact_k() {
    int n = 16 * 262144;
    for (int idx = blockIdx.x * blockDim.x + threadIdx.x; idx < n; idx += gridDim.x * blockDim.x) {
        int b = idx >> 18;
        float v = g_mag[idx];
        unsigned bits = __float_as_uint(v);
        if ((int)(bits >> 19) >= g_thresh[b]) {
            int p = atomicAdd(&g_cnt[b], 1);
            if (p < CAP) g_cand[b * CAP + p] = v;
        }
    }
}

__global__ void __launch_bounds__(512) sortsel_k() {
    __shared__ float s[4096];
    __shared__ float bv[512];
    __shared__ int   bi[512];
    int b = blockIdx.x, tid = threadIdx.x;
    int n = min(g_cnt[b], CAP);
    if (n <= 4096) {
        int size = 128;
        while (size < n) size <<= 1;
        for (int i = tid; i < size; i += 512) s[i] = (i < n) ? g_cand[b * CAP + i] : -FLT_MAX;
        __syncthreads();
        for (int k = 2; k <= size; k <<= 1) {
            for (int j = k >> 1; j > 0; j >>= 1) {
                for (int i = tid; i < size; i += 512) {
                    int ixj = i ^ j;
                    if (ixj > i) {
                        float a = s[i], c = s[ixj];
                        if ((a > c) == ((i & k) == 0)) { s[i] = c; s[ixj] = a; }
                    }
                }
                __syncthreads();
            }
        }
        if (tid < 128) g_dom[b * 128 + tid] = s[size - 1 - tid];
    } else {
        for (int r = 0; r < 128; ++r) {
            float mv = -FLT_MAX; int mi = 0;
            for (int i = tid; i < n; i += 512) {
                float v = g_cand[b * CAP + i];
                if (v > mv) { mv = v; mi = i; }
            }
            bv[tid] = mv; bi[tid] = mi;
            __syncthreads();
            for (int st = 256; st > 0; st >>= 1) {
                if (tid < st && bv[tid + st] > bv[tid]) { bv[tid] = bv[tid + st]; bi[tid] = bi[tid + st]; }
                __syncthreads();
            }
            if (tid == 0) {
                g_dom[b * 128 + r] = bv[0];
                g_cand[b * CAP + bi[0]] = -FLT_MAX;
            }
            __syncthreads();
        }
    }
}

// ===================== sims =====================
__global__ void __launch_bounds__(64) sims_k(const float* __restrict__ rec) {
    __shared__ float dm[128];
    __shared__ float red[64];
    int b = blockIdx.x, tid = threadIdx.x;
    dm[tid] = g_dom[b * 128 + tid];
    dm[tid + 64] = g_dom[b * 128 + 64 + tid];
    __syncthreads();
    red[tid] = dm[tid] * dm[tid] + dm[tid + 64] * dm[tid + 64];
    __syncthreads();
    for (int st = 32; st > 0; st >>= 1) {
        if (tid < st) red[tid] += red[tid + st];
        __syncthreads();
    }
    float nd = fmaxf(sqrtf(red[0]), 1e-12f);
    const float* r = rec + tid * 128;
    float dot = 0.f, nr = 0.f;
    #pragma unroll 4
    for (int k = 0; k < 128; ++k) {
        float rv = r[k];
        dot = fmaf(dm[k], rv, dot);
        nr = fmaf(rv, rv, nr);
    }
    g_sims[b * 64 + tid] = dot / (nd * fmaxf(sqrtf(nr), 1e-12f));
}

// ===================== conv1 (grad fused) + maxpool2 =====================
__global__ void __launch_bounds__(256) conv1pool_k(const float* __restrict__ img,
                                                   const float* __restrict__ w,
                                                   const float* __restrict__ bias) {
    __shared__ float imgs[36][68];
    __shared__ __align__(16) float gin[2][34][68];
    __shared__ float wsh[32][18];
    __shared__ float bsh[32];
    int b = blockIdx.z;
    int CY = blockIdx.y * 32, CX = blockIdx.x * 64;
    int PY = blockIdx.y * 16, PX = blockIdx.x * 32;
    int tid = threadIdx.x;
    const float* ip = img + ((size_t)b << 18);
    for (int i = tid; i < 36 * 68; i += 256) {
        int r = i / 68, c = i % 68;
        int gy = CY - 2 + r, gx = CX - 2 + c;
        imgs[r][c] = ((unsigned)gy < 512u && (unsigned)gx < 512u) ? ip[(gy << 9) | gx] : 0.f;
    }
    for (int i = tid; i < 576; i += 256) wsh[i / 18][i % 18] = w[i];
    if (tid < 32) bsh[tid] = bias[tid];
    __syncthreads();
    for (int i = tid; i < 34 * 66; i += 256) {
        int r = i / 66, x = i % 66;
        int gy = CY - 1 + r, gx = CX - 1 + x;
        float gm = 0.f, go = 0.f;
        if ((unsigned)gy < 512u && (unsigned)gx < 512u) {
            int ly = r + 1, lx = x + 1;
            float gyv, gxv;
            if (gy == 0)        gyv = imgs[ly + 1][lx] - imgs[ly][lx];
            else if (gy == 511) gyv = imgs[ly][lx] - imgs[ly - 1][lx];
            else                gyv = 0.5f * (imgs[ly + 1][lx] - imgs[ly - 1][lx]);
            if (gx == 0)        gxv = imgs[ly][lx + 1] - imgs[ly][lx];
            else if (gx == 511) gxv = imgs[ly][lx] - imgs[ly][lx - 1];
            else                gxv = 0.5f * (imgs[ly][lx + 1] - imgs[ly][lx - 1]);
            gm = sqrtf(gxv * gxv + gyv * gyv);
            go = atan2f(gyv, gxv);
        }
        gin[0][r][x] = gm;
        gin[1][r][x] = go;
    }
    __syncthreads();

    int ppy = tid >> 4, ppx = (tid & 15) * 2;
    int cy0 = ppy * 2, cx0 = ppx * 2;
    float rin[2][4][6];
    #pragma unroll
    for (int c = 0; c < 2; ++c)
        #pragma unroll
        for (int r = 0; r < 4; ++r) {
            const float* bp = &gin[c][cy0 + r][cx0];
            float4 v4 = *(const float4*)bp;
            float2 v2 = *(const float2*)(bp + 4);
            rin[c][r][0] = v4.x; rin[c][r][1] = v4.y; rin[c][r][2] = v4.z; rin[c][r][3] = v4.w;
            rin[c][r][4] = v2.x; rin[c][r][5] = v2.y;
        }
    size_t obase = ((size_t)(b * 32) * 256 + (PY + ppy)) * 256 + (PX + ppx);
    for (int oc = 0; oc < 32; ++oc) {
        float wl[2][9];
        #pragma unroll
        for (int c = 0; c < 2; ++c)
            #pragma unroll
            for (int t = 0; t < 9; ++t) wl[c][t] = wsh[oc][c * 9 + t];
        float bb = bsh[oc];
        #pragma unroll
        for (int pp = 0; pp < 2; ++pp) {
            float vmax = -FLT_MAX;
            #pragma unroll
            for (int r = 0; r < 2; ++r)
                #pragma unroll
                for (int cc = 0; cc < 2; ++cc) {
                    float v = bb;
                    #pragma unroll
                    for (int c = 0; c < 2; ++c)
                        #pragma unroll
                        for (int ky = 0; ky < 3; ++ky)
                            #pragma unroll
                            for (int kx = 0; kx < 3; ++kx)
                                v = fmaf(rin[c][r + ky][2 * pp + cc + kx], wl[c][ky * 3 + kx], v);
                    vmax = fmaxf(vmax, v);
                }
            g_h1[obase + (size_t)oc * 65536 + pp] = fmaxf(vmax, 0.f);
        }
    }
}

// ===================== conv2 via mma.sync bf16x3 tap-GEMMs + pool =====================
// Grid 2048 = 16b x 2 oc-halves x 4 x-quarters x 16 y-groups; 256 thr (8 warps).
// Warp = 16 px x 2 y-rows (M=32) x 32 oc; warps 0-3 rows (y,y+1), warps 4-7 rows (y+2,y+3).
// A staged interleaved hi/lo uint2, 6-row ring, icp-stride 68 (2*68=136 mod 32=8 -> conflict-free LDS.64).
// B packed uint4 {bh0,bh1,bl0,bl1}, row stride 12 uint4 (conflict-free LDS.128); loaded once per (tap,nt,kc),
// feeds 6 MMAs (both y-rows) -> B smem traffic halved vs R14.
#define C2_SA    0          // uint2[6*1088] = 52224 B
#define C2_BP    52224      // uint4, stride 12: 3456*16 = 55296 B
#define C2_BIAS  107520     // 32 floats
#define C2_SMEM  107776

__global__ void __launch_bounds__(256, 2) conv2mma_k(const float* __restrict__ w,
                                                     const float* __restrict__ bias) {
    extern __shared__ char smem[];
    uint2* sA     = (uint2*)(smem + C2_SA);
    uint4* BP     = (uint4*)(smem + C2_BP);
    float* bias_s = (float*)(smem + C2_BIAS);
    int tid = threadIdx.x, wp = tid >> 5, l = tid & 31;
    int bx = blockIdx.x;
    int b = bx >> 7;
    int rest = bx & 127;
    int oh = rest >> 6;
    int r2 = rest & 63;
    int xq = r2 >> 4, yg = r2 & 15;
    int x0 = xq * 64, y0 = yg * 16;

    if (tid < 32) bias_s[tid] = bias[oh * 32 + tid];
    for (int idx = tid; idx < 2304; idx += 256) {
        int quad = idx & 3, kc = (idx >> 2) & 1, rem = idx >> 3;
        int nl = rem & 31, tap = rem >> 5;
        int n = oh * 32 + nl;
        int ku0 = kc * 8 + quad, ku1 = ku0 + 4;
        float f0 = w[n * 288 + (2 * ku0) * 9 + tap];
        float f1 = w[n * 288 + (2 * ku0 + 1) * 9 + tap];
        float f2 = w[n * 288 + (2 * ku1) * 9 + tap];
        float f3 = w[n * 288 + (2 * ku1 + 1) * 9 + tap];
        uint4 c;
        split2(f0, f1, c.x, c.z);
        split2(f2, f3, c.y, c.w);
        BP[(tap * 32 + nl) * 12 + kc * 4 + quad] = c;
    }

    int quad = l & 3, mrow = l >> 2;
    int rh = wp >> 2;            // row-half: 0 -> rows (y,y+1), 1 -> (y+2,y+3)
    int pxl = (wp & 3) * 16;

    auto stage_row = [&](int gy) {
        int slot = gy % 6; if (slot < 0) slot += 6;
        bool inb = (unsigned)gy < 256u;
        for (int i = tid; i < 16 * 66; i += 256) {
            int icp = i / 66, j = i % 66;
            int gx = x0 - 1 + j;
            float f0 = 0.f, f1 = 0.f;
            if (inb && (unsigned)gx < 256u) {
                size_t gb = (((size_t)(b * 32 + 2 * icp)) * 256 + gy) * 256 + gx;
                f0 = g_h1[gb];
                f1 = g_h1[gb + 65536];
            }
            unsigned hi, lo;
            split2(f0, f1, hi, lo);
            sA[slot * 1088 + icp * 68 + j] = make_uint2(hi, lo);
        }
    };
    stage_row(y0 - 1);
    stage_row(y0);

    float pacc[4][2];
    #pragma unroll
    for (int nt = 0; nt < 4; ++nt) { pacc[nt][0] = 0.f; pacc[nt][1] = 0.f; }

    for (int t = 0; t < 4; ++t) {
        int ybase = y0 + 4 * t;
        stage_row(ybase + 1);
        stage_row(ybase + 2);
        stage_row(ybase + 3);
        stage_row(ybase + 4);
        __syncthreads();

        int sbase = (ybase - 1) % 6; if (sbase < 0) sbase += 6;   // slot of row ybase-1
        float acc0[4][4], acc1[4][4];
        #pragma unroll
        for (int nt = 0; nt < 4; ++nt)
            #pragma unroll
            for (int q = 0; q < 4; ++q) { acc0[nt][q] = 0.f; acc1[nt][q] = 0.f; }

        #pragma unroll
        for (int tap = 0; tap < 9; ++tap) {
            int r = tap / 3, dx = tap % 3;
            int s0 = sbase + 2 * rh + r; if (s0 >= 6) s0 -= 6;    // row y = ybase+2rh, gy = y+r-1
            int s1 = s0 + 1;             if (s1 >= 6) s1 -= 6;    // row y+1
            int j0 = pxl + dx + mrow;
            #pragma unroll
            for (int kc = 0; kc < 2; ++kc) {
                int boff = (kc * 8 + quad) * 68 + j0;
                int b0i = s0 * 1088 + boff;
                int b1i = s1 * 1088 + boff;
                uint2 u0 = sA[b0i], u1 = sA[b0i + 8], u2 = sA[b0i + 272], u3 = sA[b0i + 280];
                uint2 v0 = sA[b1i], v1 = sA[b1i + 8], v2 = sA[b1i + 272], v3 = sA[b1i + 280];
                unsigned AH0[4] = {u0.x, u1.x, u2.x, u3.x};
                unsigned AL0[4] = {u0.y, u1.y, u2.y, u3.y};
                unsigned AH1[4] = {v0.x, v1.x, v2.x, v3.x};
                unsigned AL1[4] = {v0.y, v1.y, v2.y, v3.y};
                #pragma unroll
                for (int nt = 0; nt < 4; ++nt) {
                    int nl = nt * 8 + mrow;
                    uint4 bb = BP[(tap * 32 + nl) * 12 + kc * 4 + quad];
                    unsigned bh[2] = {bb.x, bb.y};
                    unsigned bl[2] = {bb.z, bb.w};
                    mma16816(acc0[nt], AH0, bh);
                    mma16816(acc0[nt], AL0, bh);
                    mma16816(acc0[nt], AH0, bl);
                    mma16816(acc1[nt], AH1, bh);
                    mma16816(acc1[nt], AL1, bh);
                    mma16816(acc1[nt], AH1, bl);
                }
            }
        }
        #pragma unroll
        for (int nt = 0; nt < 4; ++nt) {
            int ol = nt * 8 + quad * 2;
            float b0 = bias_s[ol], b1 = bias_s[ol + 1];
            pacc[nt][0] += fmaxf(acc0[nt][0] + b0, 0.f) + fmaxf(acc0[nt][2] + b0, 0.f)
                         + fmaxf(acc1[nt][0] + b0, 0.f) + fmaxf(acc1[nt][2] + b0, 0.f);
            pacc[nt][1] += fmaxf(acc0[nt][1] + b1, 0.f) + fmaxf(acc0[nt][3] + b1, 0.f)
                         + fmaxf(acc1[nt][1] + b1, 0.f) + fmaxf(acc1[nt][3] + b1, 0.f);
        }
        __syncthreads();
    }

    int cell = (y0 >> 6) * 4 + xq;
    #pragma unroll
    for (int nt = 0; nt < 4; ++nt) {
        float v0 = pacc[nt][0], v1 = pacc[nt][1];
        v0 += __shfl_xor_sync(0xffffffffu, v0, 4);
        v1 += __shfl_xor_sync(0xffffffffu, v1, 4);
        v0 += __shfl_xor_sync(0xffffffffu, v0, 8);
        v1 += __shfl_xor_sync(0xffffffffu, v1, 8);
        v0 += __shfl_xor_sync(0xffffffffu, v0, 16);
        v1 += __shfl_xor_sync(0xffffffffu, v1, 16);
        if (l < 4) {
            int oc0 = oh * 32 + nt * 8 + l * 2;
            atomicAdd(&g_pool[b * 1024 + oc0 * 16 + cell], v0);
            atomicAdd(&g_pool[b * 1024 + (oc0 + 1) * 16 + cell], v1);
        }
    }
}

// ===================== fuse =====================
__global__ void __launch_bounds__(256) fuse_k(
    const float* __restrict__ fc1_w, const float* __restrict__ fc1_b,
    const float* __restrict__ fc2_w, const float* __restrict__ fc2_b,
    const float* __restrict__ ln_g, const float* __restrict__ ln_b,
    float* __restrict__ out)
{
    __shared__ float comb[1091];
    __shared__ float z[512];
    __shared__ float z2[128];
    __shared__ float stats[2];
    int b = blockIdx.x, tid = threadIdx.x;
    for (int i = tid; i < 64; i += 256) {
        float v = g_sims[b * 64 + i];
        comb[i] = v;
        out[b * 64 + i] = v;
    }
    for (int i = tid; i < 1024; i += 256) {
        float v = g_pool[b * 1024 + i] * (1.f / 4096.f);
        comb[64 + i] = v;
        out[1024 + b * 1024 + i] = v;
    }
    if (tid == 0) {
        const double N = 262144.0;
        double mean = g_psum[b] / N;
        double var = (g_psumsq[b] - N * mean * mean) / (N - 1.0);
        float ent = 0.f;
        for (int k = 0; k < 64; ++k) {
            float h = (float)g_hist[b * 64 + k] * (1.f / 262144.f);
            ent -= h * logf(h + 1e-10f);
        }
        comb[1088] = (float)mean;
        comb[1089] = (float)sqrt(var);
        comb[1090] = ent;
        out[17408 + b * 3 + 0] = comb[1088];
        out[17408 + b * 3 + 1] = comb[1089];
        out[17408 + b * 3 + 2] = comb[1090];
    }
    __syncthreads();
    for (int j = tid; j < 512; j += 256) {
        const float* wr = fc1_w + (size_t)j * 1091;
        float a0 = fc1_b[j];
        #pragma unroll 4
        for (int k = 0; k < 1091; ++k) a0 = fmaf(comb[k], wr[k], a0);
        z[j] = fmaxf(a0, 0.f);
    }
    __syncthreads();
    if (tid < 128) {
        const float* wr = fc2_w + (size_t)tid * 512;
        float a0 = fc2_b[tid];
        #pragma unroll 4
        for (int k = 0; k < 512; ++k) a0 = fmaf(z[k], wr[k], a0);
        z2[tid] = a0;
    }
    __syncthreads();
    if (tid == 0) {
        float mu = 0.f;
        for (int k = 0; k < 128; ++k) mu += z2[k];
        mu *= (1.f / 128.f);
        float var = 0.f;
        for (int k = 0; k < 128; ++k) { float d = z2[k] - mu; var += d * d; }
        var *= (1.f / 128.f);
        stats[0] = mu;
        stats[1] = rsqrtf(var + 1e-5f);
    }
    __syncthreads();
    if (tid < 128)
        out[17456 + b * 128 + tid] = (z2[tid] - stats[0]) * stats[1] * ln_g[tid] + ln_b[tid];
}

// ===================== launch =====================
extern "C" void kernel_launch(void* const* d_in, const int* in_sizes, int n_in,
                              void* d_out, int out_size) {
    const float* image = (const float*)d_in[0];
    const float* rec   = (const float*)d_in[1];
    const float* c1w   = (const float*)d_in[2];
    const float* c1b   = (const float*)d_in[3];
    const float* c2w   = (const float*)d_in[4];
    const float* c2b   = (const float*)d_in[5];
    const float* fc1w  = (const float*)d_in[6];
    const float* fc1b  = (const float*)d_in[7];
    const float* fc2w  = (const float*)d_in[8];
    const float* fc2b  = (const float*)d_in[9];
    const float* lng   = (const float*)d_in[10];
    const float* lnb   = (const float*)d_in[11];
    float* out = (float*)d_out;

    cudaFuncSetAttribute(conv2mma_k, cudaFuncAttributeMaxDynamicSharedMemorySize, C2_SMEM);

    // ordered so conv2mma_k sits at the ncu-captured launch index (3)
    zero_k<<<64, 256>>>();                                   // 0
    conv1pool_k<<<dim3(8, 16, 16), 256>>>(image, c1w, c1b);  // 1
    fft_rows_k<<<16 * 128, 256>>>(image);                    // 2
    conv2mma_k<<<2048, 256, C2_SMEM>>>(c2w, c2b);            // 3  <- profiled
    fft_cols_k<<<16 * 256, 256>>>();                         // 4
    maghist_k<<<256, 256>>>();                               // 5
    thresh_k<<<16, 32>>>();                                  // 6
    compact_k<<<1024, 256>>>();                              // 7
    sortsel_k<<<16, 512>>>();                                // 8
    sims_k<<<16, 64>>>(rec);                                 // 9
    fuse_k<<<16, 256>>>(fc1w, fc1b, fc2w, fc2b, lng, lnb, out); // 10
}

// round 16
// speedup vs baseline: 1.1891x; 1.1891x over previous
#include <cuda_runtime.h>
#include <cuda_bf16.h>
#include <stdint.h>
#include <math.h>
#include <float.h>

#define PI_F 3.14159265358979323846f
#define CAP 32768

// ===================== static scratch =====================
__device__ float2 g_spec[16 * 512 * 512];
__device__ float  g_mag [16 * 512 * 512];
__device__ float  g_h1  [16 * 32 * 256 * 256];
__device__ float  g_cand[16 * CAP];
__device__ int    g_mhist[16 * 4096];
__device__ int    g_thresh[16];
__device__ int    g_cnt[16];
__device__ float  g_dom [16 * 128];
__device__ float  g_sims[16 * 64];
__device__ float  g_pool[16 * 64 * 16];
__device__ double g_psum[16];
__device__ double g_psumsq[16];
__device__ int    g_hist[16 * 64];

// ===================== mma helpers =====================
__device__ __forceinline__ void split2(float f0, float f1, unsigned& hi, unsigned& lo) {
    unsigned b0 = __float_as_uint(f0) & 0xFFFF0000u;
    unsigned b1 = __float_as_uint(f1) & 0xFFFF0000u;
    hi = (b0 >> 16) | b1;
    float l0 = f0 - __uint_as_float(b0);
    float l1 = f1 - __uint_as_float(b1);
    asm("cvt.rn.bf16x2.f32 %0, %1, %2;" : "=r"(lo) : "f"(l1), "f"(l0));
}
__device__ __forceinline__ void mma16816(float* c, const unsigned* a, const unsigned* b) {
    asm volatile("mma.sync.aligned.m16n8k16.row.col.f32.bf16.bf16.f32 "
        "{%0,%1,%2,%3}, {%4,%5,%6,%7}, {%8,%9}, {%0,%1,%2,%3};"
        : "+f"(c[0]), "+f"(c[1]), "+f"(c[2]), "+f"(c[3])
        : "r"(a[0]), "r"(a[1]), "r"(a[2]), "r"(a[3]), "r"(b[0]), "r"(b[1]));
}

// ===================== init =====================
__global__ void zero_k() {
    int tid = blockIdx.x * blockDim.x + threadIdx.x;
    int nt = gridDim.x * blockDim.x;
    for (int i = tid; i < 16 * 64 * 16; i += nt) g_pool[i] = 0.f;
    for (int i = tid; i < 16 * 64; i += nt) g_hist[i] = 0;
    for (int i = tid; i < 16 * 4096; i += nt) g_mhist[i] = 0;
    for (int i = tid; i < 16; i += nt) { g_psum[i] = 0.0; g_psumsq[i] = 0.0; g_cnt[i] = 0; }
}

// ===================== batched 512-pt FFT (256 threads, 4 FFTs per block) =====================
__device__ __forceinline__ void fft512x4(float2 (*s)[512], const float2* tw) {
    int tid = threadIdx.x;
    __syncthreads();
    #pragma unroll
    for (int f = 0; f < 4; ++f)
        for (int i = tid; i < 512; i += 256) {
            int j = __brev(i) >> 23;
            if (j > i) { float2 t = s[f][i]; s[f][i] = s[f][j]; s[f][j] = t; }
        }
    __syncthreads();
    #pragma unroll
    for (int st = 0; st < 9; ++st) {
        int half = 1 << st;
        int pos = tid & (half - 1);
        int i0 = ((tid >> st) << (st + 1)) + pos;
        int i1 = i0 + half;
        float2 w = tw[pos << (8 - st)];
        #pragma unroll
        for (int f = 0; f < 4; ++f) {
            float2 a = s[f][i0], b = s[f][i1];
            float2 t = make_float2(w.x * b.x - w.y * b.y, w.x * b.y + w.y * b.x);
            s[f][i0] = make_float2(a.x + t.x, a.y + t.y);
            s[f][i1] = make_float2(a.x - t.x, a.y - t.y);
        }
        __syncthreads();
    }
}

// rows: real-pair trick — 2 real rows per complex FFT, 4 FFTs per block = 8 rows/block.
__global__ void __launch_bounds__(256) fft_rows_k(const float* __restrict__ img) {
    __shared__ float2 s[4][512];
    __shared__ float2 tw[256];
    int b = blockIdx.x >> 6, rg = blockIdx.x & 63;
    int row0 = rg * 8;
    int tid = threadIdx.x;
    const float* p = img + (((size_t)b << 9) + row0) * 512;
    for (int i = tid; i < 512; i += 256) {
        #pragma unroll
        for (int f = 0; f < 4; ++f)
            s[f][i] = make_float2(p[f * 1024 + i], p[f * 1024 + 512 + i]);
    }
    { float sc, cc; sincosf(-2.f * PI_F * (float)tid / 512.f, &sc, &cc); tw[tid] = make_float2(cc, sc); }
    fft512x4(s, tw);
    __syncthreads();
    for (int k = tid; k < 512; k += 256) {
        int nk = (512 - k) & 511;
        #pragma unroll
        for (int f = 0; f < 4; ++f) {
            float2 A = s[f][k], B = s[f][nk];
            float2 X = make_float2(0.5f * (A.x + B.x), 0.5f * (A.y - B.y));
            float2 Y = make_float2(0.5f * (A.y + B.y), 0.5f * (B.x - A.x));
            size_t base = (((size_t)(b * 512 + k)) << 9) + row0 + 2 * f;
            g_spec[base] = X;
            g_spec[base + 1] = Y;
        }
    }
}

// cols: 4 complex columns per block; phase stats + magnitude histogram fused.
__global__ void __launch_bounds__(256) fft_cols_k() {
    __shared__ float2 s[4][512];
    __shared__ float2 tw[256];
    __shared__ float rsum[256], rsq[256];
    __shared__ int lhist[64];
    __shared__ int mh[4096];
    int b = blockIdx.x >> 7;
    int tid = threadIdx.x;
    size_t base0 = ((size_t)blockIdx.x) << 11;   // 4 columns x 512
    for (int i = tid; i < 512; i += 256) {
        #pragma unroll
        for (int f = 0; f < 4; ++f)
            s[f][i] = g_spec[base0 + f * 512 + i];
    }
    { float sc, cc; sincosf(-2.f * PI_F * (float)tid / 512.f, &sc, &cc); tw[tid] = make_float2(cc, sc); }
    if (tid < 64) lhist[tid] = 0;
    for (int i = tid; i < 4096; i += 256) mh[i] = 0;
    fft512x4(s, tw);
    __syncthreads();
    float lsum = 0.f, lsq = 0.f;
    #pragma unroll
    for (int f = 0; f < 4; ++f)
        for (int i = tid; i < 512; i += 256) {
            float2 v = s[f][i];
            float m = sqrtf(v.x * v.x + v.y * v.y);
            g_mag[base0 + f * 512 + i] = m;
            atomicAdd(&mh[__float_as_uint(m) >> 19], 1);
            float ph = atan2f(v.y, v.x);
            lsum += ph; lsq += ph * ph;
            int bin = (int)floorf((ph + PI_F) * (64.f / (2.f * PI_F)));
            bin = min(max(bin, 0), 63);
            atomicAdd(&lhist[bin], 1);
        }
    rsum[tid] = lsum; rsq[tid] = lsq;
    __syncthreads();
    for (int st = 128; st > 0; st >>= 1) {
        if (tid < st) { rsum[tid] += rsum[tid + st]; rsq[tid] += rsq[tid + st]; }
        __syncthreads();
    }
    if (tid == 0) {
        atomicAdd(&g_psum[b], (double)rsum[0]);
        atomicAdd(&g_psumsq[b], (double)rsq[0]);
    }
    if (tid < 64) atomicAdd(&g_hist[b * 64 + tid], lhist[tid]);
    for (int i = tid; i < 4096; i += 256)
        if (mh[i]) atomicAdd(&g_mhist[b * 4096 + i], mh[i]);
}

// ===================== exact top-128 (threshold from histogram) =====================
__global__ void thresh_k() {
    int b = blockIdx.x;
    if (threadIdx.x == 0) {
        int acc = 0, t = 0;
        for (int i = 4095; i >= 0; --i) {
            acc += g_mhist[b * 4096 + i];
            if (acc >= 128) { t = i; break; }
        }
        g_thresh[b] = t;
    }
}

__global__ void __launch_bounds__(256) compact_k() {
    int n = 16 * 262144;
    for (int idx = blockIdx.x * blockDim.x + threadIdx.x; idx < n; idx += gridDim.x * blockDim.x) {
        int b = idx >> 18;
        float v = g_mag[idx];
        unsigned bits = __float_as_uint(v);
        if ((int)(bits >> 19) >= g_thresh[b]) {
            int p = atomicAdd(&g_cnt[b], 1);
            if (p < CAP) g_cand[b * CAP + p] = v;
        }
    }
}

__global__ void __launch_bounds__(512) sortsel_k() {
    __shared__ float s[4096];
    __shared__ float bv[512];
    __shared__ int   bi[512];
    int b = blockIdx.x, tid = threadIdx.x;
    int n = min(g_cnt[b], CAP);
    if (n <= 4096) {
        int size = 128;
        while (size < n) size <<= 1;
        for (int i = tid; i < size; i += 512) s[i] = (i < n) ? g_cand[b * CAP + i] : -FLT_MAX;
        __syncthreads();
        for (int k = 2; k <= size; k <<= 1) {
            for (int j = k >> 1; j > 0; j >>= 1) {
                for (int i = tid; i < size; i += 512) {
                    int ixj = i ^ j;
                    if (ixj > i) {
                        float a = s[i], c = s[ixj];
                        if ((a > c) == ((i & k) == 0)) { s[i] = c; s[ixj] = a; }
                    }
                }
                __syncthreads();
            }
        }
        if (tid < 128) g_dom[b * 128 + tid] = s[size - 1 - tid];
    } else {
        for (int r = 0; r < 128; ++r) {
            float mv = -FLT_MAX; int mi = 0;
            for (int i = tid; i < n; i += 512) {
                float v = g_cand[b * CAP + i];
                if (v > mv) { mv = v; mi = i; }
            }
            bv[tid] = mv; bi[tid] = mi;
            __syncthreads();
            for (int st = 256; st > 0; st >>= 1) {
                if (tid < st && bv[tid + st] > bv[tid]) { bv[tid] = bv[tid + st]; bi[tid] = bi[tid + st]; }
                __syncthreads();
            }
            if (tid == 0) {
                g_dom[b * 128 + r] = bv[0];
                g_cand[b * CAP + bi[0]] = -FLT_MAX;
            }
            __syncthreads();
        }
    }
}

// ===================== sims =====================
__global__ void __launch_bounds__(64) sims_k(const float* __restrict__ rec) {
    __shared__ float dm[128];
    __shared__ float red[64];
    int b = blockIdx.x, tid = threadIdx.x;
    dm[tid] = g_dom[b * 128 + tid];
    dm[tid + 64] = g_dom[b * 128 + 64 + tid];
    __syncthreads();
    red[tid] = dm[tid] * dm[tid] + dm[tid + 64] * dm[tid + 64];
    __syncthreads();
    for (int st = 32; st > 0; st >>= 1) {
        if (tid < st) red[tid] += red[tid + st];
        __syncthreads();
    }
    float nd = fmaxf(sqrtf(red[0]), 1e-12f);
    const float* r = rec + tid * 128;
    float dot = 0.f, nr = 0.f;
    #pragma unroll 4
    for (int k = 0; k < 128; ++k) {
        float rv = r[k];
        dot = fmaf(dm[k], rv, dot);
        nr = fmaf(rv, rv, nr);
    }
    g_sims[b * 64 + tid] = dot / (nd * fmaxf(sqrtf(nr), 1e-12f));
}

// ===================== conv1 (grad fused) + maxpool2 =====================
__global__ void __launch_bounds__(256) conv1pool_k(const float* __restrict__ img,
                                                   const float* __restrict__ w,
                                                   const float* __restrict__ bias) {
    __shared__ float imgs[36][68];
    __shared__ __align__(16) float gin[2][34][68];
    __shared__ float wsh[32][18];
    __shared__ float bsh[32];
    int b = blockIdx.z;
    int CY = blockIdx.y * 32, CX = blockIdx.x * 64;
    int PY = blockIdx.y * 16, PX = blockIdx.x * 32;
    int tid = threadIdx.x;
    const float* ip = img + ((size_t)b << 18);
    for (int i = tid; i < 36 * 68; i += 256) {
        int r = i / 68, c = i % 68;
        int gy = CY - 2 + r, gx = CX - 2 + c;
        imgs[r][c] = ((unsigned)gy < 512u && (unsigned)gx < 512u) ? ip[(gy << 9) | gx] : 0.f;
    }
    for (int i = tid; i < 576; i += 256) wsh[i / 18][i % 18] = w[i];
    if (tid < 32) bsh[tid] = bias[tid];
    __syncthreads();
    for (int i = tid; i < 34 * 66; i += 256) {
        int r = i / 66, x = i % 66;
        int gy = CY - 1 + r, gx = CX - 1 + x;
        float gm = 0.f, go = 0.f;
        if ((unsigned)gy < 512u && (unsigned)gx < 512u) {
            int ly = r + 1, lx = x + 1;
            float gyv, gxv;
            if (gy == 0)        gyv = imgs[ly + 1][lx] - imgs[ly][lx];
            else if (gy == 511) gyv = imgs[ly][lx] - imgs[ly - 1][lx];
            else                gyv = 0.5f * (imgs[ly + 1][lx] - imgs[ly - 1][lx]);
            if (gx == 0)        gxv = imgs[ly][lx + 1] - imgs[ly][lx];
            else if (gx == 511) gxv = imgs[ly][lx] - imgs[ly][lx - 1];
            else                gxv = 0.5f * (imgs[ly][lx + 1] - imgs[ly][lx - 1]);
            gm = sqrtf(gxv * gxv + gyv * gyv);
            go = atan2f(gyv, gxv);
        }
        gin[0][r][x] = gm;
        gin[1][r][x] = go;
    }
    __syncthreads();

    int ppy = tid >> 4, ppx = (tid & 15) * 2;
    int cy0 = ppy * 2, cx0 = ppx * 2;
    float rin[2][4][6];
    #pragma unroll
    for (int c = 0; c < 2; ++c)
        #pragma unroll
        for (int r = 0; r < 4; ++r) {
            const float* bp = &gin[c][cy0 + r][cx0];
            float4 v4 = *(const float4*)bp;
            float2 v2 = *(const float2*)(bp + 4);
            rin[c][r][0] = v4.x; rin[c][r][1] = v4.y; rin[c][r][2] = v4.z; rin[c][r][3] = v4.w;
            rin[c][r][4] = v2.x; rin[c][r][5] = v2.y;
        }
    size_t obase = ((size_t)(b * 32) * 256 + (PY + ppy)) * 256 + (PX + ppx);
    for (int oc = 0; oc < 32; ++oc) {
        float wl[2][9];
        #pragma unroll
        for (int c = 0; c < 2; ++c)
            #pragma unroll
            for (int t = 0; t < 9; ++t) wl[c][t] = wsh[oc][c * 9 + t];
        float bb = bsh[oc];
        #pragma unroll
        for (int pp = 0; pp < 2; ++pp) {
            float vmax = -FLT_MAX;
            #pragma unroll
            for (int r = 0; r < 2; ++r)
                #pragma unroll
                for (int cc = 0; cc < 2; ++cc) {
                    float v = bb;
                    #pragma unroll
                    for (int c = 0; c < 2; ++c)
                        #pragma unroll
                        for (int ky = 0; ky < 3; ++ky)
                            #pragma unroll
                            for (int kx = 0; kx < 3; ++kx)
                                v = fmaf(rin[c][r + ky][2 * pp + cc + kx], wl[c][ky * 3 + kx], v);
                    vmax = fmaxf(vmax, v);
                }
            g_h1[obase + (size_t)oc * 65536 + pp] = fmaxf(vmax, 0.f);
        }
    }
}

// ===================== conv2 via mma.sync bf16x3 tap-GEMMs + pool (R14 version) =====================
#define C2_SAH   0
#define C2_SAL   26112
#define C2_BP    52224
#define C2_BIAS  107520
#define C2_SMEM  107776

__global__ void __launch_bounds__(256, 2) conv2mma_k(const float* __restrict__ w,
                                                     const float* __restrict__ bias) {
    extern __shared__ char smem[];
    unsigned* sAH    = (unsigned*)(smem + C2_SAH);
    unsigned* sAL    = (unsigned*)(smem + C2_SAL);
    uint4*    BP     = (uint4*)(smem + C2_BP);
    float*    bias_s = (float*)(smem + C2_BIAS);
    int tid = threadIdx.x, wp = tid >> 5, l = tid & 31;
    int bx = blockIdx.x;
    int b = bx >> 6;
    int rest = bx & 63;
    int oh = rest >> 5;
    int r2 = rest & 31;
    int xh = r2 >> 4, yg = r2 & 15;
    int x0 = xh * 128, y0 = yg * 16;

    if (tid < 32) bias_s[tid] = bias[oh * 32 + tid];
    for (int idx = tid; idx < 2304; idx += 256) {
        int quad = idx & 3, kc = (idx >> 2) & 1, rem = idx >> 3;
        int nl = rem & 31, tap = rem >> 5;
        int n = oh * 32 + nl;
        int ku0 = kc * 8 + quad, ku1 = ku0 + 4;
        float f0 = w[n * 288 + (2 * ku0) * 9 + tap];
        float f1 = w[n * 288 + (2 * ku0 + 1) * 9 + tap];
        float f2 = w[n * 288 + (2 * ku1) * 9 + tap];
        float f3 = w[n * 288 + (2 * ku1 + 1) * 9 + tap];
        uint4 c;
        split2(f0, f1, c.x, c.z);
        split2(f2, f3, c.y, c.w);
        BP[(tap * 32 + nl) * 12 + kc * 4 + quad] = c;
    }

    int quad = l & 3, mrow = l >> 2;
    int pxl = wp * 16;

    for (int pr = 0; pr < 2; ++pr) {
        int gy = y0 - 1 + pr;
        int slot = ((gy % 3) + 3) % 3;
        bool inb = (unsigned)gy < 256u;
        for (int i = tid; i < 16 * 132; i += 256) {
            int icp = i / 132, j = i % 132;
            int gx = x0 - 1 + j;
            float f0 = 0.f, f1 = 0.f;
            if (inb && (unsigned)gx < 256u) {
                size_t gb = (((size_t)(b * 32 + 2 * icp)) * 256 + gy) * 256 + gx;
                f0 = g_h1[gb];
                f1 = g_h1[gb + 65536];
            }
            unsigned hi, lo;
            split2(f0, f1, hi, lo);
            sAH[slot * 2176 + icp * 136 + j] = hi;
            sAL[slot * 2176 + icp * 136 + j] = lo;
        }
    }

    float pacc[4][2];
    #pragma unroll
    for (int nt = 0; nt < 4; ++nt) { pacc[nt][0] = 0.f; pacc[nt][1] = 0.f; }

    for (int t = 0; t < 16; ++t) {
        int y = y0 + t;
        {
            int gy = y + 1;
            int slot = gy % 3;
            bool inb = (unsigned)gy < 256u;
            for (int i = tid; i < 16 * 132; i += 256) {
                int icp = i / 132, j = i % 132;
                int gx = x0 - 1 + j;
                float f0 = 0.f, f1 = 0.f;
                if (inb && (unsigned)gx < 256u) {
                    size_t gb = (((size_t)(b * 32 + 2 * icp)) * 256 + gy) * 256 + gx;
                    f0 = g_h1[gb];
                    f1 = g_h1[gb + 65536];
                }
                unsigned hi, lo;
                split2(f0, f1, hi, lo);
                sAH[slot * 2176 + icp * 136 + j] = hi;
                sAL[slot * 2176 + icp * 136 + j] = lo;
            }
        }
        __syncthreads();

        float acc[4][4];
        #pragma unroll
        for (int nt = 0; nt < 4; ++nt) { acc[nt][0] = 0.f; acc[nt][1] = 0.f; acc[nt][2] = 0.f; acc[nt][3] = 0.f; }

        #pragma unroll
        for (int tap = 0; tap < 9; ++tap) {
            int r = tap / 3, dx = tap % 3;
            int slot = (y + r + 2) % 3;
            int j0 = pxl + dx + mrow;
            unsigned AH[2][4], AL[2][4];
            #pragma unroll
            for (int kc = 0; kc < 2; ++kc) {
                int base = slot * 2176 + (kc * 8 + quad) * 136 + j0;
                AH[kc][0] = sAH[base];
                AH[kc][1] = sAH[base + 8];
                AH[kc][2] = sAH[base + 544];
                AH[kc][3] = sAH[base + 552];
                AL[kc][0] = sAL[base];
                AL[kc][1] = sAL[base + 8];
                AL[kc][2] = sAL[base + 544];
                AL[kc][3] = sAL[base + 552];
            }
            #pragma unroll
            for (int nt = 0; nt < 4; ++nt) {
                int nl = nt * 8 + mrow;
                int bidx = (tap * 32 + nl) * 12;
                #pragma unroll
                for (int kc = 0; kc < 2; ++kc) {
                    uint4 bb = BP[bidx + kc * 4 + quad];
                    unsigned bh[2] = {bb.x, bb.y};
                    unsigned bl[2] = {bb.z, bb.w};
                    mma16816(acc[nt], AH[kc], bh);
                    mma16816(acc[nt], AL[kc], bh);
                    mma16816(acc[nt], AH[kc], bl);
                }
            }
        }
        #pragma unroll
        for (int nt = 0; nt < 4; ++nt) {
            int ol = nt * 8 + quad * 2;
            float b0 = bias_s[ol], b1 = bias_s[ol + 1];
            pacc[nt][0] += fmaxf(acc[nt][0] + b0, 0.f) + fmaxf(acc[nt][2] + b0, 0.f);
            pacc[nt][1] += fmaxf(acc[nt][1] + b1, 0.f) + fmaxf(acc[nt][3] + b1, 0.f);
        }
        __syncthreads();
    }

    int cell = (y0 >> 6) * 4 + ((x0 + pxl) >> 6);
    #pragma unroll
    for (int nt = 0; nt < 4; ++nt) {
        float v0 = pacc[nt][0], v1 = pacc[nt][1];
        v0 += __shfl_xor_sync(0xffffffffu, v0, 4);
        v1 += __shfl_xor_sync(0xffffffffu, v1, 4);
        v0 += __shfl_xor_sync(0xffffffffu, v0, 8);
        v1 += __shfl_xor_sync(0xffffffffu, v1, 8);
        v0 += __shfl_xor_sync(0xffffffffu, v0, 16);
        v1 += __shfl_xor_sync(0xffffffffu, v1, 16);
        if (l < 4) {
            int oc0 = oh * 32 + nt * 8 + l * 2;
            atomicAdd(&g_pool[b * 1024 + oc0 * 16 + cell], v0);
            atomicAdd(&g_pool[b * 1024 + (oc0 + 1) * 16 + cell], v1);
        }
    }
}

// ===================== fuse =====================
__global__ void __launch_bounds__(256) fuse_k(
    const float* __restrict__ fc1_w, const float* __restrict__ fc1_b,
    const float* __restrict__ fc2_w, const float* __restrict__ fc2_b,
    const float* __restrict__ ln_g, const float* __restrict__ ln_b,
    float* __restrict__ out)
{
    __shared__ float comb[1091];
    __shared__ float z[512];
    __shared__ float z2[128];
    __shared__ float stats[2];
    int b = blockIdx.x, tid = threadIdx.x;
    for (int i = tid; i < 64; i += 256) {
        float v = g_sims[b * 64 + i];
        comb[i] = v;
        out[b * 64 + i] = v;
    }
    for (int i = tid; i < 1024; i += 256) {
        float v = g_pool[b * 1024 + i] * (1.f / 4096.f);
        comb[64 + i] = v;
        out[1024 + b * 1024 + i] = v;
    }
    if (tid == 0) {
        const double N = 262144.0;
        double mean = g_psum[b] / N;
        double var = (g_psumsq[b] - N * mean * mean) / (N - 1.0);
        float ent = 0.f;
        for (int k = 0; k < 64; ++k) {
            float h = (float)g_hist[b * 64 + k] * (1.f / 262144.f);
            ent -= h * logf(h + 1e-10f);
        }
        comb[1088] = (float)mean;
        comb[1089] = (float)sqrt(var);
        comb[1090] = ent;
        out[17408 + b * 3 + 0] = comb[1088];
        out[17408 + b * 3 + 1] = comb[1089];
        out[17408 + b * 3 + 2] = comb[1090];
    }
    __syncthreads();
    for (int j = tid; j < 512; j += 256) {
        const float* wr = fc1_w + (size_t)j * 1091;
        float a0 = fc1_b[j];
        #pragma unroll 4
        for (int k = 0; k < 1091; ++k) a0 = fmaf(comb[k], wr[k], a0);
        z[j] = fmaxf(a0, 0.f);
    }
    __syncthreads();
    if (tid < 128) {
        const float* wr = fc2_w + (size_t)tid * 512;
        float a0 = fc2_b[tid];
        #pragma unroll 4
        for (int k = 0; k < 512; ++k) a0 = fmaf(z[k], wr[k], a0);
        z2[tid] = a0;
    }
    __syncthreads();
    if (tid == 0) {
        float mu = 0.f;
        for (int k = 0; k < 128; ++k) mu += z2[k];
        mu *= (1.f / 128.f);
        float var = 0.f;
        for (int k = 0; k < 128; ++k) { float d = z2[k] - mu; var += d * d; }
        var *= (1.f / 128.f);
        stats[0] = mu;
        stats[1] = rsqrtf(var + 1e-5f);
    }
    __syncthreads();
    if (tid < 128)
        out[17456 + b * 128 + tid] = (z2[tid] - stats[0]) * stats[1] * ln_g[tid] + ln_b[tid];
}

// ===================== launch =====================
extern "C" void kernel_launch(void* const* d_in, const int* in_sizes, int n_in,
                              void* d_out, int out_size) {
    const float* image = (const float*)d_in[0];
    const float* rec   = (const float*)d_in[1];
    const float* c1w   = (const float*)d_in[2];
    const float* c1b   = (const float*)d_in[3];
    const float* c2w   = (const float*)d_in[4];
    const float* c2b   = (const float*)d_in[5];
    const float* fc1w  = (const float*)d_in[6];
    const float* fc1b  = (const float*)d_in[7];
    const float* fc2w  = (const float*)d_in[8];
    const float* fc2b  = (const float*)d_in[9];
    const float* lng   = (const float*)d_in[10];
    const float* lnb   = (const float*)d_in[11];
    float* out = (float*)d_out;

    cudaFuncSetAttribute(conv2mma_k, cudaFuncAttributeMaxDynamicSharedMemorySize, C2_SMEM);

    // ordered so conv1pool_k sits at the ncu-captured launch index (3)
    zero_k<<<64, 256>>>();                                   // 0
    fft_rows_k<<<16 * 64, 256>>>(image);                     // 1
    fft_cols_k<<<16 * 128, 256>>>();                         // 2
    conv1pool_k<<<dim3(8, 16, 16), 256>>>(image, c1w, c1b);  // 3  <- profiled
    conv2mma_k<<<1024, 256, C2_SMEM>>>(c2w, c2b);            // 4
    thresh_k<<<16, 32>>>();                                  // 5
    compact_k<<<1024, 256>>>();                              // 6
    sortsel_k<<<16, 512>>>();                                // 7
    sims_k<<<16, 64>>>(rec);                                 // 8
    fuse_k<<<16, 256>>>(fc1w, fc1b, fc2w, fc2b, lng, lnb, out); // 9
}